// round 10
// baseline (speedup 1.0000x reference)
#include <cuda_runtime.h>
#include <cstdint>

// Problem-shape maxima (fixed by the dataset)
#define NMAX   50000
#define EMAX   800000
#define ETMAX  (EMAX + NMAX)      // edges + self loops
#define HEADS  4
#define HC1    128                // heads * 32
#define HC2    256                // heads * 64
#define NEG_SLOPE 0.2f
#define GAT_EPS 1e-16f
#define CHUNK  256

// ---------------- scratch (static device globals; no allocation) ------------
__device__ float g_h1 [NMAX * HC1];
__device__ float g_y1 [NMAX * HC1];
__device__ float g_h2 [NMAX * HC2];
__device__ float g_asrc[NMAX * HEADS];
__device__ float g_adst[NMAX * HEADS];
__device__ float g_e   [ETMAX * HEADS];
__device__ int2  g_sd  [ETMAX];
__device__ int2  g_ssd [ETMAX];
__device__ int   g_cnt [NMAX + 1];
__device__ int   g_cur [NMAX + 1];
__device__ int   g_part[CHUNK];

// ---------------- helpers ---------------------------------------------------
__device__ __forceinline__ float lrelu(float x) {
    return x > 0.0f ? x : NEG_SLOPE * x;
}
__device__ __forceinline__ void fma4(float4& a, float s, float4 v) {
    a.x = fmaf(s, v.x, a.x); a.y = fmaf(s, v.y, a.y);
    a.z = fmaf(s, v.z, a.z); a.w = fmaf(s, v.w, a.w);
}
// packed f32x2 FMA: acc = x2 * w2 + acc  (both lanes)
__device__ __forceinline__ void fma_f32x2(unsigned long long& acc,
                                          unsigned long long x2,
                                          unsigned long long w2) {
    asm("fma.rn.f32x2 %0, %1, %2, %0;" : "+l"(acc) : "l"(x2), "l"(w2));
}
__device__ __forceinline__ unsigned long long dup_bits(float x) {
    unsigned int u = __float_as_uint(x);
    return ((unsigned long long)u << 32) | u;
}

// ---------------- prep: dtype sniff + (src,dst) pairs + histogram -----------
// cnt must be zeroed before this kernel (memsetAsync on the same stream).
__global__ void prep_kernel(const int* __restrict__ ei, int E, int Nn,
                            int2* __restrict__ sd, int* __restrict__ cnt) {
    // per-block dtype sniff: with int64 data every odd 32-bit word (high half)
    // of the first 512 words is zero; with int32 they are src indices.
    unsigned int w = 0;
    if (threadIdx.x < 256)
        w = ((const unsigned int*)ei)[2 * threadIdx.x + 1];
    int is64 = __syncthreads_or(w != 0u) ? 0 : 1;

    int e = blockIdx.x * blockDim.x + threadIdx.x;
    int Et = E + Nn;
    if (e >= Et) return;
    int s, d;
    if (e < E) {
        if (is64) {
            s = (int)((const long long*)ei)[e];
            d = (int)((const long long*)ei)[(long long)E + e];
        } else {
            s = ei[e];
            d = ei[E + e];
        }
    } else {
        s = d = e - E;
    }
    sd[e] = make_int2(s, d);
    atomicAdd(&cnt[d], 1);
}

// ---------------- 3-phase parallel exclusive scan over cnt[0..Nn) -----------
__global__ void scan_partial(const int* __restrict__ cnt, int* __restrict__ part, int Nn) {
    __shared__ int s[CHUNK];
    int i = blockIdx.x * CHUNK + threadIdx.x;
    s[threadIdx.x] = (i < Nn) ? cnt[i] : 0;
    __syncthreads();
#pragma unroll
    for (int o = CHUNK / 2; o > 0; o >>= 1) {
        if (threadIdx.x < o) s[threadIdx.x] += s[threadIdx.x + o];
        __syncthreads();
    }
    if (threadIdx.x == 0) part[blockIdx.x] = s[0];
}
__global__ void scan_tops(int* __restrict__ part, int nb, int* __restrict__ cnt, int Nn) {
    __shared__ int s[CHUNK];
    int t = threadIdx.x;
    int v = (t < nb) ? part[t] : 0;
    s[t] = v;
    __syncthreads();
#pragma unroll
    for (int o = 1; o < CHUNK; o <<= 1) {
        int u = (t >= o) ? s[t - o] : 0;
        __syncthreads();
        s[t] += u;
        __syncthreads();
    }
    if (t < nb) part[t] = s[t] - v;
    if (t == CHUNK - 1) cnt[Nn] = s[CHUNK - 1];
}
__global__ void scan_final(int* __restrict__ cnt, int* __restrict__ cur,
                           const int* __restrict__ part, int Nn) {
    __shared__ int s[CHUNK];
    int i = blockIdx.x * CHUNK + threadIdx.x;
    int t = threadIdx.x;
    int v = (i < Nn) ? cnt[i] : 0;
    s[t] = v;
    __syncthreads();
#pragma unroll
    for (int o = 1; o < CHUNK; o <<= 1) {
        int u = (t >= o) ? s[t - o] : 0;
        __syncthreads();
        s[t] += u;
        __syncthreads();
    }
    if (i < Nn) {
        int ex = part[blockIdx.x] + s[t] - v;
        cnt[i] = ex;
        cur[i] = ex;
    }
}

__global__ void place_kernel(const int2* __restrict__ sd, int Et,
                             int* __restrict__ cur, int2* __restrict__ ssd) {
    int e = blockIdx.x * blockDim.x + threadIdx.x;
    if (e >= Et) return;
    int2 p = sd[e];
    int pos = atomicAdd(&cur[p.y], 1);
    ssd[pos] = p;
}

// ---------------- tiled GEMM: pre-duplicated X pairs, f32x2 mainloop --------
// Y[M,NOUT] = X[M,128] @ W[128,NOUT]; block tile 64 x 128.
// Xd[r][k] holds (x,x) 8-byte pairs (dup done at staging, no MOVs in loop).
// W staged in two K-halves.  smem = 97KB -> 2 blocks/SM.
#define XDS 130
template<int NOUT>
__global__ void gemm_tiled(const float* __restrict__ X,
                           const float* __restrict__ W,
                           float* __restrict__ Y, int M) {
    extern __shared__ float smem[];
    unsigned long long (*Xd)[XDS] =
        (unsigned long long (*)[XDS])smem;                  // [64][130] pairs
    float (*Ws)[128] = (float (*)[128])(smem + 64 * XDS * 2); // [64][128]

    const int row0 = blockIdx.x * 64;
    const int c0   = blockIdx.y * 128;
    const int tid  = threadIdx.x;
    const int tx = tid & 15, ty = tid >> 4;

    // stage X as duplicated pairs (full K = 128)
#pragma unroll
    for (int i = 0; i < 8; i++) {
        int idx = tid + i * 256;
        int r = idx >> 5, kq = idx & 31;
        float4 v = (row0 + r < M) ? ((const float4*)X)[(size_t)(row0 + r) * 32 + kq]
                                  : make_float4(0.f, 0.f, 0.f, 0.f);
        ulonglong2 a, b;
        a.x = dup_bits(v.x); a.y = dup_bits(v.y);
        b.x = dup_bits(v.z); b.y = dup_bits(v.w);
        *(ulonglong2*)&Xd[r][kq * 4]     = a;
        *(ulonglong2*)&Xd[r][kq * 4 + 2] = b;
    }

    unsigned long long acc[4][4];
#pragma unroll
    for (int ri = 0; ri < 4; ri++)
#pragma unroll
        for (int j = 0; j < 4; j++) acc[ri][j] = 0ULL;

#pragma unroll
    for (int half = 0; half < 2; half++) {
        __syncthreads();
#pragma unroll
        for (int i = 0; i < 8; i++) {
            int idx = tid + i * 256;
            int k = idx >> 5, cq = idx & 31;
            *(float4*)&Ws[k][cq * 4] =
                *(const float4*)&W[(size_t)(half * 64 + k) * NOUT + c0 + cq * 4];
        }
        __syncthreads();

#pragma unroll 4
        for (int kk = 0; kk < 64; kk++) {
            int k = half * 64 + kk;
            unsigned long long w2[4];
#pragma unroll
            for (int j = 0; j < 4; j++)
                w2[j] = *(const unsigned long long*)&Ws[kk][tx * 8 + j * 2];
            unsigned long long x2[4];
#pragma unroll
            for (int ri = 0; ri < 4; ri++) x2[ri] = Xd[ty * 4 + ri][k];
#pragma unroll
            for (int ri = 0; ri < 4; ri++) {
                fma_f32x2(acc[ri][0], x2[ri], w2[0]);
                fma_f32x2(acc[ri][1], x2[ri], w2[1]);
                fma_f32x2(acc[ri][2], x2[ri], w2[2]);
                fma_f32x2(acc[ri][3], x2[ri], w2[3]);
            }
        }
    }

#pragma unroll
    for (int ri = 0; ri < 4; ri++) {
        int r = row0 + ty * 4 + ri;
        if (r < M) {
            union { unsigned long long u[2]; float4 f; } o0, o1;
            o0.u[0] = acc[ri][0]; o0.u[1] = acc[ri][1];
            o1.u[0] = acc[ri][2]; o1.u[1] = acc[ri][3];
            *(float4*)&Y[(size_t)r * NOUT + c0 + tx * 8]     = o0.f;
            *(float4*)&Y[(size_t)r * NOUT + c0 + tx * 8 + 4] = o1.f;
        }
    }
}
#define GEMM_SMEM (64 * XDS * 8 + 64 * 128 * 4)

// ---------------- per-node attention coefficients (warp per node) -----------
template<int HC>
__global__ void att_kernel(const float* __restrict__ H,
                           const float* __restrict__ av_src,
                           const float* __restrict__ av_dst,
                           float* __restrict__ osrc,
                           float* __restrict__ odst, int Nn) {
    const int w    = threadIdx.x >> 5;
    const int lane = threadIdx.x & 31;
    const int n    = blockIdx.x * 8 + w;
    if (n >= Nn) return;
    constexpr int NV = HC / 128;
    const float4* h4 = (const float4*)(H + (size_t)n * HC);
    const float4* s4 = (const float4*)av_src;
    const float4* d4 = (const float4*)av_dst;
    float ps = 0.f, pd = 0.f;
#pragma unroll
    for (int v = 0; v < NV; v++) {
        int i = lane * NV + v;
        float4 h = h4[i], a = s4[i], b = d4[i];
        ps += h.x * a.x + h.y * a.y + h.z * a.z + h.w * a.w;
        pd += h.x * b.x + h.y * b.y + h.z * b.z + h.w * b.w;
    }
#pragma unroll
    for (int o = 4; o > 0; o >>= 1) {
        ps += __shfl_down_sync(0xffffffffu, ps, o);
        pd += __shfl_down_sync(0xffffffffu, pd, o);
    }
    if ((lane & 7) == 0) {
        int h = lane >> 3;
        osrc[n * HEADS + h] = ps;
        odst[n * HEADS + h] = pd;
    }
}

// ---------------- edge pass: ev = exp(lrelu(asrc+adst)) over sorted edges ---
__global__ void edge_exp_kernel(const int2* __restrict__ ssd, int Et,
                                const float* __restrict__ asrc,
                                const float* __restrict__ adst,
                                float* __restrict__ ebuf) {
    int e = blockIdx.x * blockDim.x + threadIdx.x;
    if (e >= Et) return;
    int2 p = ssd[e];
    float4 as = ((const float4*)asrc)[p.x];
    float4 ad = ((const float4*)adst)[p.y];
    float4 ev;
    ev.x = expf(lrelu(as.x + ad.x));
    ev.y = expf(lrelu(as.y + ad.y));
    ev.z = expf(lrelu(as.z + ad.z));
    ev.w = expf(lrelu(as.w + ad.w));
    ((float4*)ebuf)[e] = ev;
}

// ---------------- warp-per-node gather-reduce -------------------------------
template<int HC, int MODE>
__global__ void gather_warp(const int2* __restrict__ ssd,
                            const int*  __restrict__ off,
                            const float* __restrict__ H,
                            const float* __restrict__ ebuf,
                            const float* __restrict__ bias,
                            float* __restrict__ Y, int Nn) {
    const int n = (blockIdx.x * blockDim.x + threadIdx.x) >> 5;
    if (n >= Nn) return;
    const int lane = threadIdx.x & 31;
    const int head = lane >> 3;
    constexpr int NV = HC / 128;

    int pos = off[n];
    const int end = off[n + 1];

    float4 acc[NV];
#pragma unroll
    for (int v = 0; v < NV; v++) acc[v] = make_float4(0.f, 0.f, 0.f, 0.f);
    float sume = 0.f;

    for (; pos + 4 <= end; pos += 4) {
        int s0 = ssd[pos].x, s1 = ssd[pos + 1].x, s2 = ssd[pos + 2].x, s3 = ssd[pos + 3].x;
        float e0 = __ldg(&ebuf[(pos    ) * 4 + head]);
        float e1 = __ldg(&ebuf[(pos + 1) * 4 + head]);
        float e2 = __ldg(&ebuf[(pos + 2) * 4 + head]);
        float e3 = __ldg(&ebuf[(pos + 3) * 4 + head]);
        const float4* h0 = (const float4*)(H + (size_t)s0 * HC);
        const float4* h1 = (const float4*)(H + (size_t)s1 * HC);
        const float4* h2 = (const float4*)(H + (size_t)s2 * HC);
        const float4* h3 = (const float4*)(H + (size_t)s3 * HC);
#pragma unroll
        for (int v = 0; v < NV; v++) {
            int i = lane * NV + v;
            float4 a0 = h0[i], a1 = h1[i], a2 = h2[i], a3 = h3[i];
            fma4(acc[v], e0, a0);
            fma4(acc[v], e1, a1);
            fma4(acc[v], e2, a2);
            fma4(acc[v], e3, a3);
        }
        sume += (e0 + e1) + (e2 + e3);
    }
    for (; pos < end; pos++) {
        int s0 = ssd[pos].x;
        float e0 = __ldg(&ebuf[pos * 4 + head]);
        const float4* h0 = (const float4*)(H + (size_t)s0 * HC);
#pragma unroll
        for (int v = 0; v < NV; v++) fma4(acc[v], e0, h0[lane * NV + v]);
        sume += e0;
    }

    const float inv = 1.0f / (sume + GAT_EPS);

    if (MODE == 0) {
        float4 v = acc[0];
        float4 b4 = ((const float4*)bias)[lane];
        v.x = v.x * inv + b4.x; v.y = v.y * inv + b4.y;
        v.z = v.z * inv + b4.z; v.w = v.w * inv + b4.w;
        v.x = v.x > 0.f ? v.x : expm1f(v.x);
        v.y = v.y > 0.f ? v.y : expm1f(v.y);
        v.z = v.z > 0.f ? v.z : expm1f(v.z);
        v.w = v.w > 0.f ? v.w : expm1f(v.w);
        ((float4*)(Y + (size_t)n * HC))[lane] = v;
    } else {
        float vv[8];
#pragma unroll
        for (int v = 0; v < NV; v++) {
            vv[v * 4 + 0] = acc[v].x * inv;
            vv[v * 4 + 1] = acc[v].y * inv;
            vv[v * 4 + 2] = acc[v].z * inv;
            vv[v * 4 + 3] = acc[v].w * inv;
        }
#pragma unroll
        for (int j = 0; j < 8; j++) {
            vv[j] += __shfl_down_sync(0xffffffffu, vv[j], 16);
            vv[j] += __shfl_down_sync(0xffffffffu, vv[j], 8);
        }
        if (lane < 8) {
            float4 b0 = ((const float4*)bias)[lane * 2];
            float4 b1 = ((const float4*)bias)[lane * 2 + 1];
            float4 o0 = make_float4(0.25f * vv[0] + b0.x, 0.25f * vv[1] + b0.y,
                                    0.25f * vv[2] + b0.z, 0.25f * vv[3] + b0.w);
            float4 o1 = make_float4(0.25f * vv[4] + b1.x, 0.25f * vv[5] + b1.y,
                                    0.25f * vv[6] + b1.z, 0.25f * vv[7] + b1.w);
            float* yp = Y + (size_t)n * 64 + lane * 8;
            *(float4*)yp = o0;
            *(float4*)(yp + 4) = o1;
        }
    }
}

// ---------------- launch ----------------------------------------------------
extern "C" void kernel_launch(void* const* d_in, const int* in_sizes, int n_in,
                              void* d_out, int out_size) {
    const float* x    = (const float*)d_in[0];
    const int*   ei   = (const int*)d_in[1];
    const float* W1   = (const float*)d_in[2];
    const float* as1  = (const float*)d_in[3];
    const float* ad1  = (const float*)d_in[4];
    const float* b1   = (const float*)d_in[5];
    const float* W2   = (const float*)d_in[6];
    const float* as2  = (const float*)d_in[7];
    const float* ad2  = (const float*)d_in[8];
    const float* b2   = (const float*)d_in[9];
    float*       out  = (float*)d_out;

    const int N  = in_sizes[0] / 128;
    const int E  = in_sizes[1] / 2;
    const int Et = E + N;

    float *p_h1, *p_y1, *p_h2, *p_as, *p_ad, *p_e;
    int2 *p_sd, *p_ssd;
    int *p_cnt, *p_cur, *p_part;
    cudaGetSymbolAddress((void**)&p_h1,  g_h1);
    cudaGetSymbolAddress((void**)&p_y1,  g_y1);
    cudaGetSymbolAddress((void**)&p_h2,  g_h2);
    cudaGetSymbolAddress((void**)&p_as,  g_asrc);
    cudaGetSymbolAddress((void**)&p_ad,  g_adst);
    cudaGetSymbolAddress((void**)&p_e,   g_e);
    cudaGetSymbolAddress((void**)&p_sd,  g_sd);
    cudaGetSymbolAddress((void**)&p_ssd, g_ssd);
    cudaGetSymbolAddress((void**)&p_cnt, g_cnt);
    cudaGetSymbolAddress((void**)&p_cur, g_cur);
    cudaGetSymbolAddress((void**)&p_part, g_part);

    static cudaStream_t s_pre = nullptr;
    static cudaEvent_t ev_fork = nullptr, ev_join = nullptr;
    if (!s_pre) {
        cudaFuncSetAttribute(gemm_tiled<HC1>, cudaFuncAttributeMaxDynamicSharedMemorySize, GEMM_SMEM);
        cudaFuncSetAttribute(gemm_tiled<HC2>, cudaFuncAttributeMaxDynamicSharedMemorySize, GEMM_SMEM);
        cudaStreamCreateWithFlags(&s_pre, cudaStreamNonBlocking);
        cudaEventCreateWithFlags(&ev_fork, cudaEventDisableTiming);
        cudaEventCreateWithFlags(&ev_join, cudaEventDisableTiming);
    }

    const int TB = 256;
    const int gemmRows = (N + 63) / 64;
    const int attGrid  = (N + 7) / 8;
    const int nb       = (N + CHUNK - 1) / CHUNK;
    const int gwGrid   = (N * 32 + TB - 1) / TB;   // warp per node

    // ---- fork: edge preprocessing on side stream, overlapped with gemm1 ----
    cudaEventRecord(ev_fork, 0);
    cudaStreamWaitEvent(s_pre, ev_fork, 0);
    cudaMemsetAsync(p_cnt, 0, (size_t)(N + 1) * sizeof(int), s_pre);
    prep_kernel<<<(Et + TB - 1) / TB, TB, 0, s_pre>>>(ei, E, N, p_sd, p_cnt);
    scan_partial<<<nb, CHUNK, 0, s_pre>>>(p_cnt, p_part, N);
    scan_tops<<<1, CHUNK, 0, s_pre>>>(p_part, nb, p_cnt, N);
    scan_final<<<nb, CHUNK, 0, s_pre>>>(p_cnt, p_cur, p_part, N);
    place_kernel<<<(Et + TB - 1) / TB, TB, 0, s_pre>>>(p_sd, Et, p_cur, p_ssd);
    cudaEventRecord(ev_join, s_pre);

    // ===== Layer 1 (main stream) =====
    gemm_tiled<HC1><<<dim3(gemmRows, 1), 256, GEMM_SMEM>>>(x, W1, p_h1, N);
    att_kernel<HC1><<<attGrid, 256>>>(p_h1, as1, ad1, p_as, p_ad, N);
    cudaStreamWaitEvent(0, ev_join, 0);
    edge_exp_kernel<<<(Et + TB - 1) / TB, TB>>>(p_ssd, Et, p_as, p_ad, p_e);
    gather_warp<HC1, 0><<<gwGrid, TB>>>(p_ssd, p_cnt, p_h1, p_e, b1, p_y1, N);

    // ===== Layer 2 =====
    gemm_tiled<HC2><<<dim3(gemmRows, 2), 256, GEMM_SMEM>>>(p_y1, W2, p_h2, N);
    att_kernel<HC2><<<attGrid, 256>>>(p_h2, as2, ad2, p_as, p_ad, N);
    edge_exp_kernel<<<(Et + TB - 1) / TB, TB>>>(p_ssd, Et, p_as, p_ad, p_e);
    gather_warp<HC2, 1><<<gwGrid, TB>>>(p_ssd, p_cnt, p_h2, p_e, b2, out, N);
}

// round 11
// speedup vs baseline: 1.1955x; 1.1955x over previous
#include <cuda_runtime.h>
#include <cstdint>

// Problem-shape maxima (fixed by the dataset)
#define NMAX   50000
#define EMAX   800000
#define ETMAX  (EMAX + NMAX)      // edges + self loops
#define HEADS  4
#define HC1    128                // heads * 32
#define HC2    256                // heads * 64
#define NEG_SLOPE 0.2f
#define GAT_EPS 1e-16f
#define CHUNK  256

// ---------------- scratch (static device globals; no allocation) ------------
__device__ float g_h1 [NMAX * HC1];
__device__ float g_y1 [NMAX * HC1];
__device__ float g_h2 [NMAX * HC2];
__device__ float g_asrc[NMAX * HEADS];
__device__ float g_adst[NMAX * HEADS];
__device__ float g_e   [ETMAX * HEADS];
__device__ int2  g_sd  [ETMAX];
__device__ int2  g_ssd [ETMAX];
__device__ int   g_cnt [NMAX + 1];
__device__ int   g_cur [NMAX + 1];
__device__ int   g_part[CHUNK];

// ---------------- helpers ---------------------------------------------------
__device__ __forceinline__ float lrelu(float x) {
    return x > 0.0f ? x : NEG_SLOPE * x;
}
__device__ __forceinline__ void fma4(float4& a, float s, float4 v) {
    a.x = fmaf(s, v.x, a.x); a.y = fmaf(s, v.y, a.y);
    a.z = fmaf(s, v.z, a.z); a.w = fmaf(s, v.w, a.w);
}
// packed f32x2 FMA: acc = x2 * w2 + acc  (both lanes)
__device__ __forceinline__ void fma_f32x2(unsigned long long& acc,
                                          unsigned long long x2,
                                          unsigned long long w2) {
    asm("fma.rn.f32x2 %0, %1, %2, %0;" : "+l"(acc) : "l"(x2), "l"(w2));
}
__device__ __forceinline__ unsigned long long dup_bits(float x) {
    unsigned long long r;
    asm("mov.b64 %0, {%1, %1};" : "=l"(r) : "r"(__float_as_uint(x)));
    return r;
}

// ---------------- prep: dtype sniff + (src,dst) pairs + histogram -----------
// cnt must be zeroed before this kernel (memsetAsync on the same stream).
__global__ void prep_kernel(const int* __restrict__ ei, int E, int Nn,
                            int2* __restrict__ sd, int* __restrict__ cnt) {
    unsigned int w = 0;
    if (threadIdx.x < 256)
        w = ((const unsigned int*)ei)[2 * threadIdx.x + 1];
    int is64 = __syncthreads_or(w != 0u) ? 0 : 1;

    int e = blockIdx.x * blockDim.x + threadIdx.x;
    int Et = E + Nn;
    if (e >= Et) return;
    int s, d;
    if (e < E) {
        if (is64) {
            s = (int)((const long long*)ei)[e];
            d = (int)((const long long*)ei)[(long long)E + e];
        } else {
            s = ei[e];
            d = ei[E + e];
        }
    } else {
        s = d = e - E;
    }
    sd[e] = make_int2(s, d);
    atomicAdd(&cnt[d], 1);
}

// ---------------- 3-phase parallel exclusive scan over cnt[0..Nn) -----------
__global__ void scan_partial(const int* __restrict__ cnt, int* __restrict__ part, int Nn) {
    __shared__ int s[CHUNK];
    int i = blockIdx.x * CHUNK + threadIdx.x;
    s[threadIdx.x] = (i < Nn) ? cnt[i] : 0;
    __syncthreads();
#pragma unroll
    for (int o = CHUNK / 2; o > 0; o >>= 1) {
        if (threadIdx.x < o) s[threadIdx.x] += s[threadIdx.x + o];
        __syncthreads();
    }
    if (threadIdx.x == 0) part[blockIdx.x] = s[0];
}
__global__ void scan_tops(int* __restrict__ part, int nb, int* __restrict__ cnt, int Nn) {
    __shared__ int s[CHUNK];
    int t = threadIdx.x;
    int v = (t < nb) ? part[t] : 0;
    s[t] = v;
    __syncthreads();
#pragma unroll
    for (int o = 1; o < CHUNK; o <<= 1) {
        int u = (t >= o) ? s[t - o] : 0;
        __syncthreads();
        s[t] += u;
        __syncthreads();
    }
    if (t < nb) part[t] = s[t] - v;
    if (t == CHUNK - 1) cnt[Nn] = s[CHUNK - 1];
}
__global__ void scan_final(int* __restrict__ cnt, int* __restrict__ cur,
                           const int* __restrict__ part, int Nn) {
    __shared__ int s[CHUNK];
    int i = blockIdx.x * CHUNK + threadIdx.x;
    int t = threadIdx.x;
    int v = (i < Nn) ? cnt[i] : 0;
    s[t] = v;
    __syncthreads();
#pragma unroll
    for (int o = 1; o < CHUNK; o <<= 1) {
        int u = (t >= o) ? s[t - o] : 0;
        __syncthreads();
        s[t] += u;
        __syncthreads();
    }
    if (i < Nn) {
        int ex = part[blockIdx.x] + s[t] - v;
        cnt[i] = ex;
        cur[i] = ex;
    }
}

__global__ void place_kernel(const int2* __restrict__ sd, int Et,
                             int* __restrict__ cur, int2* __restrict__ ssd) {
    int e = blockIdx.x * blockDim.x + threadIdx.x;
    if (e >= Et) return;
    int2 p = sd[e];
    int pos = atomicAdd(&cur[p.y], 1);
    ssd[pos] = p;
}

// ---------------- tiled GEMM: 128x128 tile, 8x8 per thread, f32x2 -----------
// Y[M,NOUT] = X[M,128] @ W[128,NOUT].  Xs fp32 [128][132], Ws [64][128]
// double-staged by K-half.  smem = 100KB -> 2 blocks/SM.
// Per k-iter/thread: 4 LDS.64(w) + 8 LDS.32(x bcast) + 32 FFMA2 -> fma-bound.
#define XPAD 132
template<int NOUT>
__global__ void __launch_bounds__(256, 2)
gemm_tiled(const float* __restrict__ X,
           const float* __restrict__ W,
           float* __restrict__ Y, int M) {
    extern __shared__ float smem[];
    float (*Xs)[XPAD] = (float (*)[XPAD])smem;                 // [128][132]
    float (*Ws)[128]  = (float (*)[128])(smem + 128 * XPAD);   // [64][128]

    const int row0 = blockIdx.x * 128;
    const int c0   = blockIdx.y * 128;
    const int tid  = threadIdx.x;
    const int tx = tid & 15, ty = tid >> 4;

    // stage X tile (128 rows x 128 k)
#pragma unroll
    for (int i = 0; i < 16; i++) {
        int idx = tid + i * 256;
        int r = idx >> 5, kq = idx & 31;
        float4 v = (row0 + r < M) ? ((const float4*)X)[(size_t)(row0 + r) * 32 + kq]
                                  : make_float4(0.f, 0.f, 0.f, 0.f);
        *(float4*)&Xs[r][kq * 4] = v;
    }

    unsigned long long acc[8][4];
#pragma unroll
    for (int ri = 0; ri < 8; ri++)
#pragma unroll
        for (int j = 0; j < 4; j++) acc[ri][j] = 0ULL;

#pragma unroll
    for (int half = 0; half < 2; half++) {
        __syncthreads();
#pragma unroll
        for (int i = 0; i < 8; i++) {
            int idx = tid + i * 256;
            int k = idx >> 5, cq = idx & 31;
            *(float4*)&Ws[k][cq * 4] =
                *(const float4*)&W[(size_t)(half * 64 + k) * NOUT + c0 + cq * 4];
        }
        __syncthreads();

#pragma unroll 2
        for (int kk = 0; kk < 64; kk++) {
            int k = half * 64 + kk;
            unsigned long long w2[4];
#pragma unroll
            for (int j = 0; j < 4; j++)
                w2[j] = *(const unsigned long long*)&Ws[kk][tx * 8 + j * 2];
#pragma unroll
            for (int ri = 0; ri < 8; ri++) {
                unsigned long long x2 = dup_bits(Xs[ty * 8 + ri][k]);
                fma_f32x2(acc[ri][0], x2, w2[0]);
                fma_f32x2(acc[ri][1], x2, w2[1]);
                fma_f32x2(acc[ri][2], x2, w2[2]);
                fma_f32x2(acc[ri][3], x2, w2[3]);
            }
        }
    }

#pragma unroll
    for (int ri = 0; ri < 8; ri++) {
        int r = row0 + ty * 8 + ri;
        if (r < M) {
            union { unsigned long long u[2]; float4 f; } o0, o1;
            o0.u[0] = acc[ri][0]; o0.u[1] = acc[ri][1];
            o1.u[0] = acc[ri][2]; o1.u[1] = acc[ri][3];
            *(float4*)&Y[(size_t)r * NOUT + c0 + tx * 8]     = o0.f;
            *(float4*)&Y[(size_t)r * NOUT + c0 + tx * 8 + 4] = o1.f;
        }
    }
}
#define GEMM_SMEM ((128 * XPAD + 64 * 128) * 4)

// ---------------- per-node attention coefficients (warp per node) -----------
template<int HC>
__global__ void att_kernel(const float* __restrict__ H,
                           const float* __restrict__ av_src,
                           const float* __restrict__ av_dst,
                           float* __restrict__ osrc,
                           float* __restrict__ odst, int Nn) {
    const int w    = threadIdx.x >> 5;
    const int lane = threadIdx.x & 31;
    const int n    = blockIdx.x * 8 + w;
    if (n >= Nn) return;
    constexpr int NV = HC / 128;
    const float4* h4 = (const float4*)(H + (size_t)n * HC);
    const float4* s4 = (const float4*)av_src;
    const float4* d4 = (const float4*)av_dst;
    float ps = 0.f, pd = 0.f;
#pragma unroll
    for (int v = 0; v < NV; v++) {
        int i = lane * NV + v;
        float4 h = h4[i], a = s4[i], b = d4[i];
        ps += h.x * a.x + h.y * a.y + h.z * a.z + h.w * a.w;
        pd += h.x * b.x + h.y * b.y + h.z * b.z + h.w * b.w;
    }
#pragma unroll
    for (int o = 4; o > 0; o >>= 1) {
        ps += __shfl_down_sync(0xffffffffu, ps, o);
        pd += __shfl_down_sync(0xffffffffu, pd, o);
    }
    if ((lane & 7) == 0) {
        int h = lane >> 3;
        osrc[n * HEADS + h] = ps;
        odst[n * HEADS + h] = pd;
    }
}

// ---------------- edge pass: ev = exp(lrelu(asrc+adst)) over sorted edges ---
__global__ void edge_exp_kernel(const int2* __restrict__ ssd, int Et,
                                const float* __restrict__ asrc,
                                const float* __restrict__ adst,
                                float* __restrict__ ebuf) {
    int e = blockIdx.x * blockDim.x + threadIdx.x;
    if (e >= Et) return;
    int2 p = ssd[e];
    float4 as = ((const float4*)asrc)[p.x];
    float4 ad = ((const float4*)adst)[p.y];
    float4 ev;
    ev.x = expf(lrelu(as.x + ad.x));
    ev.y = expf(lrelu(as.y + ad.y));
    ev.z = expf(lrelu(as.z + ad.z));
    ev.w = expf(lrelu(as.w + ad.w));
    ((float4*)ebuf)[e] = ev;
}

// ---------------- warp-per-node gather-reduce -------------------------------
template<int HC, int MODE>
__global__ void gather_warp(const int2* __restrict__ ssd,
                            const int*  __restrict__ off,
                            const float* __restrict__ H,
                            const float* __restrict__ ebuf,
                            const float* __restrict__ bias,
                            float* __restrict__ Y, int Nn) {
    const int n = (blockIdx.x * blockDim.x + threadIdx.x) >> 5;
    if (n >= Nn) return;
    const int lane = threadIdx.x & 31;
    const int head = lane >> 3;
    constexpr int NV = HC / 128;

    int pos = off[n];
    const int end = off[n + 1];

    float4 acc[NV];
#pragma unroll
    for (int v = 0; v < NV; v++) acc[v] = make_float4(0.f, 0.f, 0.f, 0.f);
    float sume = 0.f;

    for (; pos + 4 <= end; pos += 4) {
        int s0 = ssd[pos].x, s1 = ssd[pos + 1].x, s2 = ssd[pos + 2].x, s3 = ssd[pos + 3].x;
        float e0 = __ldg(&ebuf[(pos    ) * 4 + head]);
        float e1 = __ldg(&ebuf[(pos + 1) * 4 + head]);
        float e2 = __ldg(&ebuf[(pos + 2) * 4 + head]);
        float e3 = __ldg(&ebuf[(pos + 3) * 4 + head]);
        const float4* h0 = (const float4*)(H + (size_t)s0 * HC);
        const float4* h1 = (const float4*)(H + (size_t)s1 * HC);
        const float4* h2 = (const float4*)(H + (size_t)s2 * HC);
        const float4* h3 = (const float4*)(H + (size_t)s3 * HC);
#pragma unroll
        for (int v = 0; v < NV; v++) {
            int i = lane * NV + v;
            float4 a0 = h0[i], a1 = h1[i], a2 = h2[i], a3 = h3[i];
            fma4(acc[v], e0, a0);
            fma4(acc[v], e1, a1);
            fma4(acc[v], e2, a2);
            fma4(acc[v], e3, a3);
        }
        sume += (e0 + e1) + (e2 + e3);
    }
    for (; pos < end; pos++) {
        int s0 = ssd[pos].x;
        float e0 = __ldg(&ebuf[pos * 4 + head]);
        const float4* h0 = (const float4*)(H + (size_t)s0 * HC);
#pragma unroll
        for (int v = 0; v < NV; v++) fma4(acc[v], e0, h0[lane * NV + v]);
        sume += e0;
    }

    const float inv = 1.0f / (sume + GAT_EPS);

    if (MODE == 0) {
        float4 v = acc[0];
        float4 b4 = ((const float4*)bias)[lane];
        v.x = v.x * inv + b4.x; v.y = v.y * inv + b4.y;
        v.z = v.z * inv + b4.z; v.w = v.w * inv + b4.w;
        v.x = v.x > 0.f ? v.x : expm1f(v.x);
        v.y = v.y > 0.f ? v.y : expm1f(v.y);
        v.z = v.z > 0.f ? v.z : expm1f(v.z);
        v.w = v.w > 0.f ? v.w : expm1f(v.w);
        ((float4*)(Y + (size_t)n * HC))[lane] = v;
    } else {
        float vv[8];
#pragma unroll
        for (int v = 0; v < NV; v++) {
            vv[v * 4 + 0] = acc[v].x * inv;
            vv[v * 4 + 1] = acc[v].y * inv;
            vv[v * 4 + 2] = acc[v].z * inv;
            vv[v * 4 + 3] = acc[v].w * inv;
        }
#pragma unroll
        for (int j = 0; j < 8; j++) {
            vv[j] += __shfl_down_sync(0xffffffffu, vv[j], 16);
            vv[j] += __shfl_down_sync(0xffffffffu, vv[j], 8);
        }
        if (lane < 8) {
            float4 b0 = ((const float4*)bias)[lane * 2];
            float4 b1 = ((const float4*)bias)[lane * 2 + 1];
            float4 o0 = make_float4(0.25f * vv[0] + b0.x, 0.25f * vv[1] + b0.y,
                                    0.25f * vv[2] + b0.z, 0.25f * vv[3] + b0.w);
            float4 o1 = make_float4(0.25f * vv[4] + b1.x, 0.25f * vv[5] + b1.y,
                                    0.25f * vv[6] + b1.z, 0.25f * vv[7] + b1.w);
            float* yp = Y + (size_t)n * 64 + lane * 8;
            *(float4*)yp = o0;
            *(float4*)(yp + 4) = o1;
        }
    }
}

// ---------------- launch ----------------------------------------------------
extern "C" void kernel_launch(void* const* d_in, const int* in_sizes, int n_in,
                              void* d_out, int out_size) {
    const float* x    = (const float*)d_in[0];
    const int*   ei   = (const int*)d_in[1];
    const float* W1   = (const float*)d_in[2];
    const float* as1  = (const float*)d_in[3];
    const float* ad1  = (const float*)d_in[4];
    const float* b1   = (const float*)d_in[5];
    const float* W2   = (const float*)d_in[6];
    const float* as2  = (const float*)d_in[7];
    const float* ad2  = (const float*)d_in[8];
    const float* b2   = (const float*)d_in[9];
    float*       out  = (float*)d_out;

    const int N  = in_sizes[0] / 128;
    const int E  = in_sizes[1] / 2;
    const int Et = E + N;

    float *p_h1, *p_y1, *p_h2, *p_as, *p_ad, *p_e;
    int2 *p_sd, *p_ssd;
    int *p_cnt, *p_cur, *p_part;
    cudaGetSymbolAddress((void**)&p_h1,  g_h1);
    cudaGetSymbolAddress((void**)&p_y1,  g_y1);
    cudaGetSymbolAddress((void**)&p_h2,  g_h2);
    cudaGetSymbolAddress((void**)&p_as,  g_asrc);
    cudaGetSymbolAddress((void**)&p_ad,  g_adst);
    cudaGetSymbolAddress((void**)&p_e,   g_e);
    cudaGetSymbolAddress((void**)&p_sd,  g_sd);
    cudaGetSymbolAddress((void**)&p_ssd, g_ssd);
    cudaGetSymbolAddress((void**)&p_cnt, g_cnt);
    cudaGetSymbolAddress((void**)&p_cur, g_cur);
    cudaGetSymbolAddress((void**)&p_part, g_part);

    static cudaStream_t s_pre = nullptr;
    static cudaEvent_t ev_fork = nullptr, ev_join = nullptr;
    if (!s_pre) {
        cudaFuncSetAttribute(gemm_tiled<HC1>, cudaFuncAttributeMaxDynamicSharedMemorySize, GEMM_SMEM);
        cudaFuncSetAttribute(gemm_tiled<HC2>, cudaFuncAttributeMaxDynamicSharedMemorySize, GEMM_SMEM);
        cudaStreamCreateWithFlags(&s_pre, cudaStreamNonBlocking);
        cudaEventCreateWithFlags(&ev_fork, cudaEventDisableTiming);
        cudaEventCreateWithFlags(&ev_join, cudaEventDisableTiming);
    }

    const int TB = 256;
    const int gemmRows = (N + 127) / 128;
    const int attGrid  = (N + 7) / 8;
    const int nb       = (N + CHUNK - 1) / CHUNK;
    const int gwGrid   = (N * 32 + TB - 1) / TB;   // warp per node

    // ---- fork: edge preprocessing on side stream, overlapped with gemm1 ----
    cudaEventRecord(ev_fork, 0);
    cudaStreamWaitEvent(s_pre, ev_fork, 0);
    cudaMemsetAsync(p_cnt, 0, (size_t)(N + 1) * sizeof(int), s_pre);
    prep_kernel<<<(Et + TB - 1) / TB, TB, 0, s_pre>>>(ei, E, N, p_sd, p_cnt);
    scan_partial<<<nb, CHUNK, 0, s_pre>>>(p_cnt, p_part, N);
    scan_tops<<<1, CHUNK, 0, s_pre>>>(p_part, nb, p_cnt, N);
    scan_final<<<nb, CHUNK, 0, s_pre>>>(p_cnt, p_cur, p_part, N);
    place_kernel<<<(Et + TB - 1) / TB, TB, 0, s_pre>>>(p_sd, Et, p_cur, p_ssd);
    cudaEventRecord(ev_join, s_pre);

    // ===== Layer 1 (main stream) =====
    gemm_tiled<HC1><<<dim3(gemmRows, 1), 256, GEMM_SMEM>>>(x, W1, p_h1, N);
    att_kernel<HC1><<<attGrid, 256>>>(p_h1, as1, ad1, p_as, p_ad, N);
    cudaStreamWaitEvent(0, ev_join, 0);
    edge_exp_kernel<<<(Et + TB - 1) / TB, TB>>>(p_ssd, Et, p_as, p_ad, p_e);
    gather_warp<HC1, 0><<<gwGrid, TB>>>(p_ssd, p_cnt, p_h1, p_e, b1, p_y1, N);

    // ===== Layer 2 =====
    gemm_tiled<HC2><<<dim3(gemmRows, 2), 256, GEMM_SMEM>>>(p_y1, W2, p_h2, N);
    att_kernel<HC2><<<attGrid, 256>>>(p_h2, as2, ad2, p_as, p_ad, N);
    edge_exp_kernel<<<(Et + TB - 1) / TB, TB>>>(p_ssd, Et, p_as, p_ad, p_e);
    gather_warp<HC2, 1><<<gwGrid, TB>>>(p_ssd, p_cnt, p_h2, p_e, b2, out, N);
}

// round 13
// speedup vs baseline: 1.2887x; 1.0779x over previous
#include <cuda_runtime.h>
#include <cstdint>

// Problem-shape maxima (fixed by the dataset)
#define NMAX   50000
#define EMAX   800000
#define ETMAX  (EMAX + NMAX)      // edges + self loops
#define HEADS  4
#define HC1    128                // heads * 32
#define HC2    256                // heads * 64
#define NEG_SLOPE 0.2f
#define GAT_EPS 1e-16f
#define CHUNK  256

// ---------------- scratch (static device globals; no allocation) ------------
__device__ float g_h1 [NMAX * HC1];
__device__ float g_y1 [NMAX * HC1];
__device__ float g_h2 [NMAX * HC2];
__device__ float g_asrc[NMAX * HEADS];
__device__ float g_adst[NMAX * HEADS];
__device__ int2  g_sd  [ETMAX];
__device__ int   g_ssrc[ETMAX];     // src per sorted edge (dst implicit via off)
__device__ int   g_cnt [NMAX + 1];
__device__ int   g_cur [NMAX + 1];
__device__ int   g_part[CHUNK];

// ---------------- helpers ---------------------------------------------------
__device__ __forceinline__ float lrelu(float x) {
    return x > 0.0f ? x : NEG_SLOPE * x;
}
__device__ __forceinline__ void fma4(float4& a, float s, float4 v) {
    a.x = fmaf(s, v.x, a.x); a.y = fmaf(s, v.y, a.y);
    a.z = fmaf(s, v.z, a.z); a.w = fmaf(s, v.w, a.w);
}
__device__ __forceinline__ void fma_f32x2(unsigned long long& acc,
                                          unsigned long long x2,
                                          unsigned long long w2) {
    asm("fma.rn.f32x2 %0, %1, %2, %0;" : "+l"(acc) : "l"(x2), "l"(w2));
}
__device__ __forceinline__ unsigned long long dup_bits(float x) {
    unsigned long long r;
    asm("mov.b64 %0, {%1, %1};" : "=l"(r) : "r"(__float_as_uint(x)));
    return r;
}

// ---------------- prep: dtype sniff + (src,dst) pairs + histogram -----------
__global__ void prep_kernel(const int* __restrict__ ei, int E, int Nn,
                            int2* __restrict__ sd, int* __restrict__ cnt) {
    unsigned int w = 0;
    if (threadIdx.x < 256)
        w = ((const unsigned int*)ei)[2 * threadIdx.x + 1];
    int is64 = __syncthreads_or(w != 0u) ? 0 : 1;

    int e = blockIdx.x * blockDim.x + threadIdx.x;
    int Et = E + Nn;
    if (e >= Et) return;
    int s, d;
    if (e < E) {
        if (is64) {
            s = (int)((const long long*)ei)[e];
            d = (int)((const long long*)ei)[(long long)E + e];
        } else {
            s = ei[e];
            d = ei[E + e];
        }
    } else {
        s = d = e - E;
    }
    sd[e] = make_int2(s, d);
    atomicAdd(&cnt[d], 1);
}

// ---------------- 3-phase parallel exclusive scan over cnt[0..Nn) -----------
__global__ void scan_partial(const int* __restrict__ cnt, int* __restrict__ part, int Nn) {
    __shared__ int s[CHUNK];
    int i = blockIdx.x * CHUNK + threadIdx.x;
    s[threadIdx.x] = (i < Nn) ? cnt[i] : 0;
    __syncthreads();
#pragma unroll
    for (int o = CHUNK / 2; o > 0; o >>= 1) {
        if (threadIdx.x < o) s[threadIdx.x] += s[threadIdx.x + o];
        __syncthreads();
    }
    if (threadIdx.x == 0) part[blockIdx.x] = s[0];
}
__global__ void scan_tops(int* __restrict__ part, int nb, int* __restrict__ cnt, int Nn) {
    __shared__ int s[CHUNK];
    int t = threadIdx.x;
    int v = (t < nb) ? part[t] : 0;
    s[t] = v;
    __syncthreads();
#pragma unroll
    for (int o = 1; o < CHUNK; o <<= 1) {
        int u = (t >= o) ? s[t - o] : 0;
        __syncthreads();
        s[t] += u;
        __syncthreads();
    }
    if (t < nb) part[t] = s[t] - v;
    if (t == CHUNK - 1) cnt[Nn] = s[CHUNK - 1];
}
__global__ void scan_final(int* __restrict__ cnt, int* __restrict__ cur,
                           const int* __restrict__ part, int Nn) {
    __shared__ int s[CHUNK];
    int i = blockIdx.x * CHUNK + threadIdx.x;
    int t = threadIdx.x;
    int v = (i < Nn) ? cnt[i] : 0;
    s[t] = v;
    __syncthreads();
#pragma unroll
    for (int o = 1; o < CHUNK; o <<= 1) {
        int u = (t >= o) ? s[t - o] : 0;
        __syncthreads();
        s[t] += u;
        __syncthreads();
    }
    if (i < Nn) {
        int ex = part[blockIdx.x] + s[t] - v;
        cnt[i] = ex;
        cur[i] = ex;
    }
}

__global__ void place_kernel(const int2* __restrict__ sd, int Et,
                             int* __restrict__ cur, int* __restrict__ ssrc) {
    int e = blockIdx.x * blockDim.x + threadIdx.x;
    if (e >= Et) return;
    int2 p = sd[e];
    int pos = atomicAdd(&cur[p.y], 1);
    ssrc[pos] = p.x;
}

// ---------------- tiled GEMM + fused attention coefficients -----------------
// Y[M,NOUT] = X[M,128] @ W[128,NOUT]; 128x128 tile, 8x8/thread, f32x2.
// Epilogue also computes a_src[n,h], a_dst[n,h] from register accumulators:
// head channels CH align to TPH = CH/8 consecutive tx threads (shfl width).
#define XPAD 132
template<int NOUT, int CH>
__global__ void __launch_bounds__(256, 2)
gemm_tiled(const float* __restrict__ X,
           const float* __restrict__ W,
           const float* __restrict__ av_src,
           const float* __restrict__ av_dst,
           float* __restrict__ Y,
           float* __restrict__ oasrc,
           float* __restrict__ oadst, int M) {
    extern __shared__ float smem[];
    float (*Xs)[XPAD] = (float (*)[XPAD])smem;                 // [128][132]
    float (*Ws)[128]  = (float (*)[128])(smem + 128 * XPAD);   // [64][128]

    const int row0 = blockIdx.x * 128;
    const int c0   = blockIdx.y * 128;
    const int tid  = threadIdx.x;
    const int tx = tid & 15, ty = tid >> 4;

#pragma unroll
    for (int i = 0; i < 16; i++) {
        int idx = tid + i * 256;
        int r = idx >> 5, kq = idx & 31;
        float4 v = (row0 + r < M) ? ((const float4*)X)[(size_t)(row0 + r) * 32 + kq]
                                  : make_float4(0.f, 0.f, 0.f, 0.f);
        *(float4*)&Xs[r][kq * 4] = v;
    }

    unsigned long long acc[8][4];
#pragma unroll
    for (int ri = 0; ri < 8; ri++)
#pragma unroll
        for (int j = 0; j < 4; j++) acc[ri][j] = 0ULL;

#pragma unroll
    for (int half = 0; half < 2; half++) {
        __syncthreads();
#pragma unroll
        for (int i = 0; i < 8; i++) {
            int idx = tid + i * 256;
            int k = idx >> 5, cq = idx & 31;
            *(float4*)&Ws[k][cq * 4] =
                *(const float4*)&W[(size_t)(half * 64 + k) * NOUT + c0 + cq * 4];
        }
        __syncthreads();

#pragma unroll 2
        for (int kk = 0; kk < 64; kk++) {
            int k = half * 64 + kk;
            unsigned long long w2[4];
#pragma unroll
            for (int j = 0; j < 4; j++)
                w2[j] = *(const unsigned long long*)&Ws[kk][tx * 8 + j * 2];
#pragma unroll
            for (int ri = 0; ri < 8; ri++) {
                unsigned long long x2 = dup_bits(Xs[ty * 8 + ri][k]);
                fma_f32x2(acc[ri][0], x2, w2[0]);
                fma_f32x2(acc[ri][1], x2, w2[1]);
                fma_f32x2(acc[ri][2], x2, w2[2]);
                fma_f32x2(acc[ri][3], x2, w2[3]);
            }
        }
    }

    // attention coefficient vectors for this thread's 8 columns
    float avs[8], avd[8];
#pragma unroll
    for (int j = 0; j < 8; j++) {
        avs[j] = __ldg(&av_src[c0 + tx * 8 + j]);
        avd[j] = __ldg(&av_dst[c0 + tx * 8 + j]);
    }
    constexpr int TPH = CH / 8;                  // threads per head (4 or 8)
    const int head = (c0 + tx * 8) / CH;

#pragma unroll
    for (int ri = 0; ri < 8; ri++) {
        int r = row0 + ty * 8 + ri;
        union { unsigned long long u[4]; float f[8]; } o;
#pragma unroll
        for (int j = 0; j < 4; j++) o.u[j] = acc[ri][j];

        float sp = 0.f, dp = 0.f;
#pragma unroll
        for (int j = 0; j < 8; j++) {
            sp = fmaf(o.f[j], avs[j], sp);
            dp = fmaf(o.f[j], avd[j], dp);
        }
#pragma unroll
        for (int off = TPH / 2; off > 0; off >>= 1) {
            sp += __shfl_down_sync(0xffffffffu, sp, off, TPH);
            dp += __shfl_down_sync(0xffffffffu, dp, off, TPH);
        }
        if (r < M) {
            *(float4*)&Y[(size_t)r * NOUT + c0 + tx * 8]     = *(float4*)&o.f[0];
            *(float4*)&Y[(size_t)r * NOUT + c0 + tx * 8 + 4] = *(float4*)&o.f[4];
            if ((tx & (TPH - 1)) == 0) {
                oasrc[r * HEADS + head] = sp;
                oadst[r * HEADS + head] = dp;
            }
        }
    }
}
#define GEMM_SMEM ((128 * XPAD + 64 * 128) * 4)

// ---------------- warp-per-node gather-reduce with inline softmax -----------
// Lane L covers NV float4s; head = L/8.  ev computed inline from a_src/a_dst.
// MODE 0: bias + elu -> Y[n*HC]    MODE 1: head-mean + bias -> Y[n*64]
template<int HC, int MODE>
__global__ void gather_warp(const int* __restrict__ ssrc,
                            const int*  __restrict__ off,
                            const float* __restrict__ H,
                            const float* __restrict__ asrc,
                            const float* __restrict__ adst,
                            const float* __restrict__ bias,
                            float* __restrict__ Y, int Nn) {
    const int n = (blockIdx.x * blockDim.x + threadIdx.x) >> 5;
    if (n >= Nn) return;
    const int lane = threadIdx.x & 31;
    const int head = lane >> 3;
    constexpr int NV = HC / 128;

    int pos = off[n];
    const int end = off[n + 1];
    const float ad_h = __ldg(&adst[n * HEADS + head]);

    float4 acc[NV];
#pragma unroll
    for (int v = 0; v < NV; v++) acc[v] = make_float4(0.f, 0.f, 0.f, 0.f);
    float sume = 0.f;

    for (; pos + 4 <= end; pos += 4) {
        int s0 = ssrc[pos], s1 = ssrc[pos + 1], s2 = ssrc[pos + 2], s3 = ssrc[pos + 3];
        float e0 = __expf(lrelu(__ldg(&asrc[s0 * HEADS + head]) + ad_h));
        float e1 = __expf(lrelu(__ldg(&asrc[s1 * HEADS + head]) + ad_h));
        float e2 = __expf(lrelu(__ldg(&asrc[s2 * HEADS + head]) + ad_h));
        float e3 = __expf(lrelu(__ldg(&asrc[s3 * HEADS + head]) + ad_h));
        const float4* h0 = (const float4*)(H + (size_t)s0 * HC);
        const float4* h1 = (const float4*)(H + (size_t)s1 * HC);
        const float4* h2 = (const float4*)(H + (size_t)s2 * HC);
        const float4* h3 = (const float4*)(H + (size_t)s3 * HC);
#pragma unroll
        for (int v = 0; v < NV; v++) {
            int i = lane * NV + v;
            float4 a0 = h0[i], a1 = h1[i], a2 = h2[i], a3 = h3[i];
            fma4(acc[v], e0, a0);
            fma4(acc[v], e1, a1);
            fma4(acc[v], e2, a2);
            fma4(acc[v], e3, a3);
        }
        sume += (e0 + e1) + (e2 + e3);
    }
    for (; pos < end; pos++) {
        int s0 = ssrc[pos];
        float e0 = __expf(lrelu(__ldg(&asrc[s0 * HEADS + head]) + ad_h));
        const float4* h0 = (const float4*)(H + (size_t)s0 * HC);
#pragma unroll
        for (int v = 0; v < NV; v++) fma4(acc[v], e0, h0[lane * NV + v]);
        sume += e0;
    }

    const float inv = 1.0f / (sume + GAT_EPS);

    if (MODE == 0) {
        float4 v = acc[0];
        float4 b4 = ((const float4*)bias)[lane];
        v.x = v.x * inv + b4.x; v.y = v.y * inv + b4.y;
        v.z = v.z * inv + b4.z; v.w = v.w * inv + b4.w;
        v.x = v.x > 0.f ? v.x : expm1f(v.x);
        v.y = v.y > 0.f ? v.y : expm1f(v.y);
        v.z = v.z > 0.f ? v.z : expm1f(v.z);
        v.w = v.w > 0.f ? v.w : expm1f(v.w);
        ((float4*)(Y + (size_t)n * HC))[lane] = v;
    } else {
        float vv[8];
#pragma unroll
        for (int v = 0; v < NV; v++) {
            vv[v * 4 + 0] = acc[v].x * inv;
            vv[v * 4 + 1] = acc[v].y * inv;
            vv[v * 4 + 2] = acc[v].z * inv;
            vv[v * 4 + 3] = acc[v].w * inv;
        }
#pragma unroll
        for (int j = 0; j < 8; j++) {
            vv[j] += __shfl_down_sync(0xffffffffu, vv[j], 16);
            vv[j] += __shfl_down_sync(0xffffffffu, vv[j], 8);
        }
        if (lane < 8) {
            float4 b0 = ((const float4*)bias)[lane * 2];
            float4 b1 = ((const float4*)bias)[lane * 2 + 1];
            float4 o0 = make_float4(0.25f * vv[0] + b0.x, 0.25f * vv[1] + b0.y,
                                    0.25f * vv[2] + b0.z, 0.25f * vv[3] + b0.w);
            float4 o1 = make_float4(0.25f * vv[4] + b1.x, 0.25f * vv[5] + b1.y,
                                    0.25f * vv[6] + b1.z, 0.25f * vv[7] + b1.w);
            float* yp = Y + (size_t)n * 64 + lane * 8;
            *(float4*)yp = o0;
            *(float4*)(yp + 4) = o1;
        }
    }
}

// ---------------- launch ----------------------------------------------------
extern "C" void kernel_launch(void* const* d_in, const int* in_sizes, int n_in,
                              void* d_out, int out_size) {
    const float* x    = (const float*)d_in[0];
    const int*   ei   = (const int*)d_in[1];
    const float* W1   = (const float*)d_in[2];
    const float* as1  = (const float*)d_in[3];
    const float* ad1  = (const float*)d_in[4];
    const float* b1   = (const float*)d_in[5];
    const float* W2   = (const float*)d_in[6];
    const float* as2  = (const float*)d_in[7];
    const float* ad2  = (const float*)d_in[8];
    const float* b2   = (const float*)d_in[9];
    float*       out  = (float*)d_out;

    const int N  = in_sizes[0] / 128;
    const int E  = in_sizes[1] / 2;
    const int Et = E + N;

    float *p_h1, *p_y1, *p_h2, *p_as, *p_ad;
    int2 *p_sd;
    int *p_ssrc, *p_cnt, *p_cur, *p_part;
    cudaGetSymbolAddress((void**)&p_h1,  g_h1);
    cudaGetSymbolAddress((void**)&p_y1,  g_y1);
    cudaGetSymbolAddress((void**)&p_h2,  g_h2);
    cudaGetSymbolAddress((void**)&p_as,  g_asrc);
    cudaGetSymbolAddress((void**)&p_ad,  g_adst);
    cudaGetSymbolAddress((void**)&p_sd,  g_sd);
    cudaGetSymbolAddress((void**)&p_ssrc, g_ssrc);
    cudaGetSymbolAddress((void**)&p_cnt, g_cnt);
    cudaGetSymbolAddress((void**)&p_cur, g_cur);
    cudaGetSymbolAddress((void**)&p_part, g_part);

    static cudaStream_t s_pre = nullptr;
    static cudaEvent_t ev_fork = nullptr, ev_join = nullptr;
    if (!s_pre) {
        cudaFuncSetAttribute(gemm_tiled<HC1, 32>,
                             cudaFuncAttributeMaxDynamicSharedMemorySize, GEMM_SMEM);
        cudaFuncSetAttribute(gemm_tiled<HC2, 64>,
                             cudaFuncAttributeMaxDynamicSharedMemorySize, GEMM_SMEM);
        cudaStreamCreateWithFlags(&s_pre, cudaStreamNonBlocking);
        cudaEventCreateWithFlags(&ev_fork, cudaEventDisableTiming);
        cudaEventCreateWithFlags(&ev_join, cudaEventDisableTiming);
    }

    const int TB = 256;
    const int gemmRows = (N + 127) / 128;
    const int nb       = (N + CHUNK - 1) / CHUNK;
    const int gwGrid   = (N * 32 + TB - 1) / TB;   // warp per node

    // ---- fork: edge preprocessing on side stream, overlapped with gemm1 ----
    cudaEventRecord(ev_fork, 0);
    cudaStreamWaitEvent(s_pre, ev_fork, 0);
    cudaMemsetAsync(p_cnt, 0, (size_t)(N + 1) * sizeof(int), s_pre);
    prep_kernel<<<(Et + TB - 1) / TB, TB, 0, s_pre>>>(ei, E, N, p_sd, p_cnt);
    scan_partial<<<nb, CHUNK, 0, s_pre>>>(p_cnt, p_part, N);
    scan_tops<<<1, CHUNK, 0, s_pre>>>(p_part, nb, p_cnt, N);
    scan_final<<<nb, CHUNK, 0, s_pre>>>(p_cnt, p_cur, p_part, N);
    place_kernel<<<(Et + TB - 1) / TB, TB, 0, s_pre>>>(p_sd, Et, p_cur, p_ssrc);
    cudaEventRecord(ev_join, s_pre);

    // ===== Layer 1 (main stream) =====
    gemm_tiled<HC1, 32><<<dim3(gemmRows, 1), 256, GEMM_SMEM>>>(
        x, W1, as1, ad1, p_h1, p_as, p_ad, N);
    cudaStreamWaitEvent(0, ev_join, 0);
    gather_warp<HC1, 0><<<gwGrid, TB>>>(p_ssrc, p_cnt, p_h1, p_as, p_ad, b1, p_y1, N);

    // ===== Layer 2 =====
    gemm_tiled<HC2, 64><<<dim3(gemmRows, 2), 256, GEMM_SMEM>>>(
        p_y1, W2, as2, ad2, p_h2, p_as, p_ad, N);
    gather_warp<HC2, 1><<<gwGrid, TB>>>(p_ssrc, p_cnt, p_h2, p_as, p_ad, b2, out, N);
}

// round 14
// speedup vs baseline: 1.4433x; 1.1200x over previous
#include <cuda_runtime.h>
#include <cuda_fp16.h>
#include <cstdint>

// Problem-shape maxima (fixed by the dataset)
#define NMAX   50000
#define EMAX   800000
#define ETMAX  (EMAX + NMAX)      // edges + self loops
#define HEADS  4
#define HC1    128                // heads * 32
#define HC2    256                // heads * 64
#define NEG_SLOPE 0.2f
#define GAT_EPS 1e-16f
#define CHUNK  256

// ---------------- scratch (static device globals; no allocation) ------------
__device__ __half g_h1 [NMAX * HC1];   // layer1 linear output (fp16, gathered)
__device__ float  g_y1 [NMAX * HC1];   // layer1 output after elu (fp32, gemm2 in)
__device__ __half g_h2 [NMAX * HC2];   // layer2 linear output (fp16, gathered)
__device__ float  g_asrc[NMAX * HEADS];
__device__ float  g_adst[NMAX * HEADS];
__device__ int2   g_sd  [ETMAX];
__device__ int    g_ssrc[ETMAX];
__device__ int    g_cnt [NMAX + 1];
__device__ int    g_cur [NMAX + 1];
__device__ int    g_part[CHUNK];

// ---------------- helpers ---------------------------------------------------
__device__ __forceinline__ float lrelu(float x) {
    return x > 0.0f ? x : NEG_SLOPE * x;
}
__device__ __forceinline__ void fma4(float4& a, float s, float4 v) {
    a.x = fmaf(s, v.x, a.x); a.y = fmaf(s, v.y, a.y);
    a.z = fmaf(s, v.z, a.z); a.w = fmaf(s, v.w, a.w);
}
__device__ __forceinline__ void fma_f32x2(unsigned long long& acc,
                                          unsigned long long x2,
                                          unsigned long long w2) {
    asm("fma.rn.f32x2 %0, %1, %2, %0;" : "+l"(acc) : "l"(x2), "l"(w2));
}
__device__ __forceinline__ unsigned long long dup_bits(float x) {
    unsigned long long r;
    asm("mov.b64 %0, {%1, %1};" : "=l"(r) : "r"(__float_as_uint(x)));
    return r;
}
// load NV float4s worth of fp16 H data for one lane (NV=1: 8B, NV=2: 16B)
template<int NV>
__device__ __forceinline__ void ldh(const __half* hp, int lane, float4* out) {
    if (NV == 1) {
        uint2 v = ((const uint2*)hp)[lane];
        float2 a = __half22float2(*(const __half2*)&v.x);
        float2 b = __half22float2(*(const __half2*)&v.y);
        out[0] = make_float4(a.x, a.y, b.x, b.y);
    } else {
        uint4 v = ((const uint4*)hp)[lane];
        float2 a = __half22float2(*(const __half2*)&v.x);
        float2 b = __half22float2(*(const __half2*)&v.y);
        float2 c = __half22float2(*(const __half2*)&v.z);
        float2 d = __half22float2(*(const __half2*)&v.w);
        out[0] = make_float4(a.x, a.y, b.x, b.y);
        out[1] = make_float4(c.x, c.y, d.x, d.y);
    }
}

// ---------------- prep: dtype sniff + (src,dst) pairs + histogram -----------
__global__ void prep_kernel(const int* __restrict__ ei, int E, int Nn,
                            int2* __restrict__ sd, int* __restrict__ cnt) {
    unsigned int w = 0;
    if (threadIdx.x < 256)
        w = ((const unsigned int*)ei)[2 * threadIdx.x + 1];
    int is64 = __syncthreads_or(w != 0u) ? 0 : 1;

    int e = blockIdx.x * blockDim.x + threadIdx.x;
    int Et = E + Nn;
    if (e >= Et) return;
    int s, d;
    if (e < E) {
        if (is64) {
            s = (int)((const long long*)ei)[e];
            d = (int)((const long long*)ei)[(long long)E + e];
        } else {
            s = ei[e];
            d = ei[E + e];
        }
    } else {
        s = d = e - E;
    }
    sd[e] = make_int2(s, d);
    atomicAdd(&cnt[d], 1);
}

// ---------------- 3-phase parallel exclusive scan over cnt[0..Nn) -----------
__global__ void scan_partial(const int* __restrict__ cnt, int* __restrict__ part, int Nn) {
    __shared__ int s[CHUNK];
    int i = blockIdx.x * CHUNK + threadIdx.x;
    s[threadIdx.x] = (i < Nn) ? cnt[i] : 0;
    __syncthreads();
#pragma unroll
    for (int o = CHUNK / 2; o > 0; o >>= 1) {
        if (threadIdx.x < o) s[threadIdx.x] += s[threadIdx.x + o];
        __syncthreads();
    }
    if (threadIdx.x == 0) part[blockIdx.x] = s[0];
}
__global__ void scan_tops(int* __restrict__ part, int nb, int* __restrict__ cnt, int Nn) {
    __shared__ int s[CHUNK];
    int t = threadIdx.x;
    int v = (t < nb) ? part[t] : 0;
    s[t] = v;
    __syncthreads();
#pragma unroll
    for (int o = 1; o < CHUNK; o <<= 1) {
        int u = (t >= o) ? s[t - o] : 0;
        __syncthreads();
        s[t] += u;
        __syncthreads();
    }
    if (t < nb) part[t] = s[t] - v;
    if (t == CHUNK - 1) cnt[Nn] = s[CHUNK - 1];
}
__global__ void scan_final(int* __restrict__ cnt, int* __restrict__ cur,
                           const int* __restrict__ part, int Nn) {
    __shared__ int s[CHUNK];
    int i = blockIdx.x * CHUNK + threadIdx.x;
    int t = threadIdx.x;
    int v = (i < Nn) ? cnt[i] : 0;
    s[t] = v;
    __syncthreads();
#pragma unroll
    for (int o = 1; o < CHUNK; o <<= 1) {
        int u = (t >= o) ? s[t - o] : 0;
        __syncthreads();
        s[t] += u;
        __syncthreads();
    }
    if (i < Nn) {
        int ex = part[blockIdx.x] + s[t] - v;
        cnt[i] = ex;
        cur[i] = ex;
    }
}

__global__ void place_kernel(const int2* __restrict__ sd, int Et,
                             int* __restrict__ cur, int* __restrict__ ssrc) {
    int e = blockIdx.x * blockDim.x + threadIdx.x;
    if (e >= Et) return;
    int2 p = sd[e];
    int pos = atomicAdd(&cur[p.y], 1);
    ssrc[pos] = p.x;
}

// ---------------- tiled GEMM + fused att coefs, fp16 output -----------------
// Y[M,NOUT](fp16) = X[M,128] @ W[128,NOUT]; 128x128 tile, 8x8/thread, f32x2.
// Accumulation fp32; att coefs from unrounded accumulators; single fp16 store.
#define XPAD 132
template<int NOUT, int CH>
__global__ void __launch_bounds__(256, 2)
gemm_tiled(const float* __restrict__ X,
           const float* __restrict__ W,
           const float* __restrict__ av_src,
           const float* __restrict__ av_dst,
           __half* __restrict__ Y,
           float* __restrict__ oasrc,
           float* __restrict__ oadst, int M) {
    extern __shared__ float smem[];
    float (*Xs)[XPAD] = (float (*)[XPAD])smem;                 // [128][132]
    float (*Ws)[128]  = (float (*)[128])(smem + 128 * XPAD);   // [64][128]

    const int row0 = blockIdx.x * 128;
    const int c0   = blockIdx.y * 128;
    const int tid  = threadIdx.x;
    const int tx = tid & 15, ty = tid >> 4;

#pragma unroll
    for (int i = 0; i < 16; i++) {
        int idx = tid + i * 256;
        int r = idx >> 5, kq = idx & 31;
        float4 v = (row0 + r < M) ? ((const float4*)X)[(size_t)(row0 + r) * 32 + kq]
                                  : make_float4(0.f, 0.f, 0.f, 0.f);
        *(float4*)&Xs[r][kq * 4] = v;
    }

    unsigned long long acc[8][4];
#pragma unroll
    for (int ri = 0; ri < 8; ri++)
#pragma unroll
        for (int j = 0; j < 4; j++) acc[ri][j] = 0ULL;

#pragma unroll
    for (int half = 0; half < 2; half++) {
        __syncthreads();
#pragma unroll
        for (int i = 0; i < 8; i++) {
            int idx = tid + i * 256;
            int k = idx >> 5, cq = idx & 31;
            *(float4*)&Ws[k][cq * 4] =
                *(const float4*)&W[(size_t)(half * 64 + k) * NOUT + c0 + cq * 4];
        }
        __syncthreads();

#pragma unroll 2
        for (int kk = 0; kk < 64; kk++) {
            int k = half * 64 + kk;
            unsigned long long w2[4];
#pragma unroll
            for (int j = 0; j < 4; j++)
                w2[j] = *(const unsigned long long*)&Ws[kk][tx * 8 + j * 2];
#pragma unroll
            for (int ri = 0; ri < 8; ri++) {
                unsigned long long x2 = dup_bits(Xs[ty * 8 + ri][k]);
                fma_f32x2(acc[ri][0], x2, w2[0]);
                fma_f32x2(acc[ri][1], x2, w2[1]);
                fma_f32x2(acc[ri][2], x2, w2[2]);
                fma_f32x2(acc[ri][3], x2, w2[3]);
            }
        }
    }

    float avs[8], avd[8];
#pragma unroll
    for (int j = 0; j < 8; j++) {
        avs[j] = __ldg(&av_src[c0 + tx * 8 + j]);
        avd[j] = __ldg(&av_dst[c0 + tx * 8 + j]);
    }
    constexpr int TPH = CH / 8;                  // threads per head (4 or 8)
    const int head = (c0 + tx * 8) / CH;

#pragma unroll
    for (int ri = 0; ri < 8; ri++) {
        int r = row0 + ty * 8 + ri;
        union { unsigned long long u[4]; float f[8]; } o;
#pragma unroll
        for (int j = 0; j < 4; j++) o.u[j] = acc[ri][j];

        float sp = 0.f, dp = 0.f;
#pragma unroll
        for (int j = 0; j < 8; j++) {
            sp = fmaf(o.f[j], avs[j], sp);
            dp = fmaf(o.f[j], avd[j], dp);
        }
#pragma unroll
        for (int off = TPH / 2; off > 0; off >>= 1) {
            sp += __shfl_down_sync(0xffffffffu, sp, off, TPH);
            dp += __shfl_down_sync(0xffffffffu, dp, off, TPH);
        }
        if (r < M) {
            union { __half2 h[4]; uint4 v; } ho;
#pragma unroll
            for (int j = 0; j < 4; j++)
                ho.h[j] = __floats2half2_rn(o.f[2 * j], o.f[2 * j + 1]);
            *(uint4*)&Y[(size_t)r * NOUT + c0 + tx * 8] = ho.v;
            if ((tx & (TPH - 1)) == 0) {
                oasrc[r * HEADS + head] = sp;
                oadst[r * HEADS + head] = dp;
            }
        }
    }
}
#define GEMM_SMEM ((128 * XPAD + 64 * 128) * 4)

// ---------------- warp-per-node gather-reduce, fp16 H, inline softmax -------
// MODE 0: bias + elu -> Y[n*HC] (fp32)   MODE 1: head-mean + bias -> Y[n*64]
template<int HC, int MODE>
__global__ void gather_warp(const int* __restrict__ ssrc,
                            const int*  __restrict__ off,
                            const __half* __restrict__ H,
                            const float* __restrict__ asrc,
                            const float* __restrict__ adst,
                            const float* __restrict__ bias,
                            float* __restrict__ Y, int Nn) {
    const int n = (blockIdx.x * blockDim.x + threadIdx.x) >> 5;
    if (n >= Nn) return;
    const int lane = threadIdx.x & 31;
    const int head = lane >> 3;
    constexpr int NV = HC / 128;

    int pos = off[n];
    const int end = off[n + 1];
    const float ad_h = __ldg(&adst[n * HEADS + head]);

    float4 acc[NV];
#pragma unroll
    for (int v = 0; v < NV; v++) acc[v] = make_float4(0.f, 0.f, 0.f, 0.f);
    float sume = 0.f;

    for (; pos + 4 <= end; pos += 4) {
        int s0 = ssrc[pos], s1 = ssrc[pos + 1], s2 = ssrc[pos + 2], s3 = ssrc[pos + 3];
        float e0 = __expf(lrelu(__ldg(&asrc[s0 * HEADS + head]) + ad_h));
        float e1 = __expf(lrelu(__ldg(&asrc[s1 * HEADS + head]) + ad_h));
        float e2 = __expf(lrelu(__ldg(&asrc[s2 * HEADS + head]) + ad_h));
        float e3 = __expf(lrelu(__ldg(&asrc[s3 * HEADS + head]) + ad_h));
        float4 a0[NV], a1[NV], a2[NV], a3[NV];
        ldh<NV>(H + (size_t)s0 * HC, lane, a0);
        ldh<NV>(H + (size_t)s1 * HC, lane, a1);
        ldh<NV>(H + (size_t)s2 * HC, lane, a2);
        ldh<NV>(H + (size_t)s3 * HC, lane, a3);
#pragma unroll
        for (int v = 0; v < NV; v++) {
            fma4(acc[v], e0, a0[v]);
            fma4(acc[v], e1, a1[v]);
            fma4(acc[v], e2, a2[v]);
            fma4(acc[v], e3, a3[v]);
        }
        sume += (e0 + e1) + (e2 + e3);
    }
    for (; pos < end; pos++) {
        int s0 = ssrc[pos];
        float e0 = __expf(lrelu(__ldg(&asrc[s0 * HEADS + head]) + ad_h));
        float4 a0[NV];
        ldh<NV>(H + (size_t)s0 * HC, lane, a0);
#pragma unroll
        for (int v = 0; v < NV; v++) fma4(acc[v], e0, a0[v]);
        sume += e0;
    }

    const float inv = 1.0f / (sume + GAT_EPS);

    if (MODE == 0) {
        float4 v = acc[0];
        float4 b4 = ((const float4*)bias)[lane];
        v.x = v.x * inv + b4.x; v.y = v.y * inv + b4.y;
        v.z = v.z * inv + b4.z; v.w = v.w * inv + b4.w;
        v.x = v.x > 0.f ? v.x : expm1f(v.x);
        v.y = v.y > 0.f ? v.y : expm1f(v.y);
        v.z = v.z > 0.f ? v.z : expm1f(v.z);
        v.w = v.w > 0.f ? v.w : expm1f(v.w);
        ((float4*)(Y + (size_t)n * HC))[lane] = v;
    } else {
        float vv[8];
#pragma unroll
        for (int v = 0; v < NV; v++) {
            vv[v * 4 + 0] = acc[v].x * inv;
            vv[v * 4 + 1] = acc[v].y * inv;
            vv[v * 4 + 2] = acc[v].z * inv;
            vv[v * 4 + 3] = acc[v].w * inv;
        }
#pragma unroll
        for (int j = 0; j < 8; j++) {
            vv[j] += __shfl_down_sync(0xffffffffu, vv[j], 16);
            vv[j] += __shfl_down_sync(0xffffffffu, vv[j], 8);
        }
        if (lane < 8) {
            float4 b0 = ((const float4*)bias)[lane * 2];
            float4 b1 = ((const float4*)bias)[lane * 2 + 1];
            float4 o0 = make_float4(0.25f * vv[0] + b0.x, 0.25f * vv[1] + b0.y,
                                    0.25f * vv[2] + b0.z, 0.25f * vv[3] + b0.w);
            float4 o1 = make_float4(0.25f * vv[4] + b1.x, 0.25f * vv[5] + b1.y,
                                    0.25f * vv[6] + b1.z, 0.25f * vv[7] + b1.w);
            float* yp = Y + (size_t)n * 64 + lane * 8;
            *(float4*)yp = o0;
            *(float4*)(yp + 4) = o1;
        }
    }
}

// ---------------- launch ----------------------------------------------------
extern "C" void kernel_launch(void* const* d_in, const int* in_sizes, int n_in,
                              void* d_out, int out_size) {
    const float* x    = (const float*)d_in[0];
    const int*   ei   = (const int*)d_in[1];
    const float* W1   = (const float*)d_in[2];
    const float* as1  = (const float*)d_in[3];
    const float* ad1  = (const float*)d_in[4];
    const float* b1   = (const float*)d_in[5];
    const float* W2   = (const float*)d_in[6];
    const float* as2  = (const float*)d_in[7];
    const float* ad2  = (const float*)d_in[8];
    const float* b2   = (const float*)d_in[9];
    float*       out  = (float*)d_out;

    const int N  = in_sizes[0] / 128;
    const int E  = in_sizes[1] / 2;
    const int Et = E + N;

    __half *p_h1, *p_h2;
    float *p_y1, *p_as, *p_ad;
    int2 *p_sd;
    int *p_ssrc, *p_cnt, *p_cur, *p_part;
    cudaGetSymbolAddress((void**)&p_h1,  g_h1);
    cudaGetSymbolAddress((void**)&p_y1,  g_y1);
    cudaGetSymbolAddress((void**)&p_h2,  g_h2);
    cudaGetSymbolAddress((void**)&p_as,  g_asrc);
    cudaGetSymbolAddress((void**)&p_ad,  g_adst);
    cudaGetSymbolAddress((void**)&p_sd,  g_sd);
    cudaGetSymbolAddress((void**)&p_ssrc, g_ssrc);
    cudaGetSymbolAddress((void**)&p_cnt, g_cnt);
    cudaGetSymbolAddress((void**)&p_cur, g_cur);
    cudaGetSymbolAddress((void**)&p_part, g_part);

    static cudaStream_t s_pre = nullptr;
    static cudaEvent_t ev_fork = nullptr, ev_join = nullptr;
    if (!s_pre) {
        cudaFuncSetAttribute(gemm_tiled<HC1, 32>,
                             cudaFuncAttributeMaxDynamicSharedMemorySize, GEMM_SMEM);
        cudaFuncSetAttribute(gemm_tiled<HC2, 64>,
                             cudaFuncAttributeMaxDynamicSharedMemorySize, GEMM_SMEM);
        cudaStreamCreateWithFlags(&s_pre, cudaStreamNonBlocking);
        cudaEventCreateWithFlags(&ev_fork, cudaEventDisableTiming);
        cudaEventCreateWithFlags(&ev_join, cudaEventDisableTiming);
    }

    const int TB = 256;
    const int gemmRows = (N + 127) / 128;
    const int nb       = (N + CHUNK - 1) / CHUNK;
    const int gwGrid   = (N * 32 + TB - 1) / TB;   // warp per node

    // ---- fork: edge preprocessing on side stream, overlapped with gemm1 ----
    cudaEventRecord(ev_fork, 0);
    cudaStreamWaitEvent(s_pre, ev_fork, 0);
    cudaMemsetAsync(p_cnt, 0, (size_t)(N + 1) * sizeof(int), s_pre);
    prep_kernel<<<(Et + TB - 1) / TB, TB, 0, s_pre>>>(ei, E, N, p_sd, p_cnt);
    scan_partial<<<nb, CHUNK, 0, s_pre>>>(p_cnt, p_part, N);
    scan_tops<<<1, CHUNK, 0, s_pre>>>(p_part, nb, p_cnt, N);
    scan_final<<<nb, CHUNK, 0, s_pre>>>(p_cnt, p_cur, p_part, N);
    place_kernel<<<(Et + TB - 1) / TB, TB, 0, s_pre>>>(p_sd, Et, p_cur, p_ssrc);
    cudaEventRecord(ev_join, s_pre);

    // ===== Layer 1 (main stream) =====
    gemm_tiled<HC1, 32><<<dim3(gemmRows, 1), 256, GEMM_SMEM>>>(
        x, W1, as1, ad1, p_h1, p_as, p_ad, N);
    cudaStreamWaitEvent(0, ev_join, 0);
    gather_warp<HC1, 0><<<gwGrid, TB>>>(p_ssrc, p_cnt, p_h1, p_as, p_ad, b1, p_y1, N);

    // ===== Layer 2 =====
    gemm_tiled<HC2, 64><<<dim3(gemmRows, 2), 256, GEMM_SMEM>>>(
        p_y1, W2, as2, ad2, p_h2, p_as, p_ad, N);
    gather_warp<HC2, 1><<<gwGrid, TB>>>(p_ssrc, p_cnt, p_h2, p_as, p_ad, b2, out, N);
}